// round 9
// baseline (speedup 1.0000x reference)
#include <cuda_runtime.h>
#include <cuda_bf16.h>
#include <float.h>

// Problem constants
#define B_   16
#define N_   2048
#define C_   128
#define M_   (B_ * N_)          // 32768 rows
#define KNN  8
#define NBLK 4

#define ALPHA_F    0.8888888888888888f   // 8/9
#define ONEMA_F    0.1111111111111111f   // 1/9
#define WEDGE_F    0.125f                // normalized adjacency entry (deg=8 everywhere)

typedef unsigned long long u64;
typedef unsigned int u32;

// ---------------- scratch (static device globals; no allocs allowed) ---------
__device__ float g_pts[M_ * C_];
__device__ float g_Ya [M_ * C_];   // epilogue-fused: pts + alpha * relu(pts)@WcT
__device__ float g_Yg [M_ * C_];
__device__ float g_Uc [M_ * 6];
__device__ float g_Ug [M_ * 6];
__device__ int   g_nbr[M_ * KNN];  // [0]=self, [1..7]=kNN (within-batch indices)
// precomputed bf16 splits of Wc (HMMA path only): [blk][128*128]
__device__ __nv_bfloat16 g_Wsh[NBLK * C_ * C_];
__device__ __nv_bfloat16 g_Wsl[NBLK * C_ * C_];

// ======================= helpers =============================================
__device__ __forceinline__ u32 smem_u32(const void* p) {
    u32 a;
    asm("{ .reg .u64 t; cvta.to.shared.u64 t, %1; cvt.u32.u64 %0, t; }"
        : "=r"(a) : "l"(p));
    return a;
}
__device__ __forceinline__ float bfhi(float x) {
    return __bfloat162float(__float2bfloat16_rn(x));
}
__device__ __forceinline__ u32 packbf(float lo, float hi) {
    u32 r; asm("cvt.rn.bf16x2.f32 %0, %1, %2;" : "=r"(r) : "f"(hi), "f"(lo));
    return r;
}
__device__ __forceinline__ void ldsm_x4(u32 r[4], u32 addr) {
    asm volatile("ldmatrix.sync.aligned.m8n8.x4.shared.b16 {%0,%1,%2,%3}, [%4];"
        : "=r"(r[0]), "=r"(r[1]), "=r"(r[2]), "=r"(r[3]) : "r"(addr));
}
__device__ __forceinline__ void mma16816(float c[4], const u32 a[4], const u32 b[2]) {
    asm volatile("mma.sync.aligned.m16n8k16.row.col.f32.bf16.bf16.f32 "
        "{%0,%1,%2,%3}, {%4,%5,%6,%7}, {%8,%9}, {%0,%1,%2,%3};"
        : "+f"(c[0]), "+f"(c[1]), "+f"(c[2]), "+f"(c[3])
        : "r"(a[0]), "r"(a[1]), "r"(a[2]), "r"(a[3]), "r"(b[0]), "r"(b[1]));
}
__device__ __forceinline__ void ffma2(u64 &acc, u64 a, u64 b) {
    asm("fma.rn.f32x2 %0, %1, %2, %0;" : "+l"(acc) : "l"(a), "l"(b));
}
__device__ __forceinline__ float2 unpack2(u64 v) {
    float2 f; asm("mov.b64 {%0, %1}, %2;" : "=f"(f.x), "=f"(f.y) : "l"(v)); return f;
}
__device__ __forceinline__ u64 dup2(float a) {
    u64 r; asm("mov.b64 %0, {%1, %1};" : "=l"(r) : "f"(a)); return r;
}

// HMMA smem layout (bf16, padded stride; 64-row A tile, 128-row W tile)
#define LDB  136
#define HA_H 0
#define HA_L 17408
#define HW_H 34816
#define HW_L 69632
#define GEMM_SMEM 104448        // fits 2 CTAs/SM (209KB < 228KB)

// ---------------- 1) kNN top-8 + Wc bf16 split prep --------------------------
__global__ void knn_kernel(const float* __restrict__ xyz,
                           const float* __restrict__ Wc) {
    __shared__ float4 sP[N_];   // (x, y, z, |p|^2) interleaved -> 1 LDS.128/cand
    // fold-in: precompute Wc hi/lo bf16 split (2 elems/thread)
    {
        int gt = blockIdx.x * 256 + threadIdx.x;
        for (int i = gt; i < NBLK * C_ * C_; i += 128 * 256) {
            float w = Wc[i];
            float h = bfhi(w);
            g_Wsh[i] = __float2bfloat16_rn(h);
            g_Wsl[i] = __float2bfloat16_rn(w - h);
        }
    }
    int b = blockIdx.x >> 3;
    int qBase = (blockIdx.x & 7) * 256;
    const float* X = xyz + (size_t)b * 3 * N_;
    for (int i = threadIdx.x; i < N_; i += 256) {
        float x = X[i], y = X[N_ + i], z = X[2 * N_ + i];
        sP[i] = make_float4(x, y, z, x * x + y * y + z * z);
    }
    __syncthreads();

    int q = qBase + threadIdx.x;
    float4 qp = sP[q];
    float bd[KNN]; int bi[KNN];
#pragma unroll
    for (int s = 0; s < KNN; ++s) { bd[s] = FLT_MAX; bi[s] = 0x7fffffff; }

    for (int j = 0; j < N_; ++j) {
        float4 pj = sP[j];
        float inner = qp.x * pj.x + qp.y * pj.y + qp.z * pj.z;
        float d = (qp.w + pj.w) - 2.0f * inner;
        if (d < bd[KNN - 1]) {                   // strict <: stable tie (lower idx wins)
            bd[KNN - 1] = d; bi[KNN - 1] = j;
#pragma unroll
            for (int s = KNN - 1; s > 0; --s) {
                if (bd[s] < bd[s - 1]) {
                    float td = bd[s]; bd[s] = bd[s - 1]; bd[s - 1] = td;
                    int   ti = bi[s]; bi[s] = bi[s - 1]; bi[s - 1] = ti;
                }
            }
        }
    }
    int* outp = g_nbr + (size_t)(b * N_ + q) * KNN;
    outp[0] = q;
#pragma unroll
    for (int s = 1; s < KNN; ++s) outp[s] = bi[s];
}

// ------- 2) transpose points (B,C,N) -> pts (B,N,C), half the batch per call -
__global__ void transpose_in(const float* __restrict__ pin, int bOff) {
    __shared__ float tile[32][33];
    int b = blockIdx.z + bOff;
    int n0 = blockIdx.x * 32, c0 = blockIdx.y * 32;
    const float* src = pin + (size_t)b * C_ * N_;
    float* dst = g_pts + (size_t)b * N_ * C_;
    for (int r = threadIdx.y; r < 32; r += 8)
        tile[r][threadIdx.x] = src[(c0 + r) * N_ + n0 + threadIdx.x];
    __syncthreads();
    for (int r = threadIdx.y; r < 32; r += 8)
        dst[(n0 + r) * C_ + c0 + threadIdx.x] = tile[threadIdx.x][r];
}

// ---------------- 3) hybrid GEMM: tensor pipe + fma pipe in one launch -------
// 768 blocks. bid%3<2 -> HMMA tile (512x 64-row tiles):
//   Ya = pts + ALPHA*(relu(pts)@WcT), bf16 3-split (hh+lh+hl) on mma.sync
// bid%3==2 -> SIMT tile (256x 128-row tiles):
//   Yg = pts @ WgT, exact fp32 via packed fma.rn.f32x2
// Uniform 104.4KB dynamic smem + regs<=128 -> 2 CTAs/SM, types interleave.
__global__ __launch_bounds__(256, 2) void gemm_hybrid(const float* __restrict__ Wg,
                                                      int blk) {
    extern __shared__ char S[];
    int t = threadIdx.x;
    int wid = t >> 5, lane = t & 31;
    int bid = blockIdx.x;
    int r3 = bid % 3, trip = bid / 3;

    if (r3 < 2) {
        // ================= HMMA path: relu(pts)@WcT, 64-row tile =============
        int th = trip * 2 + r3;          // 0..511
        int row0 = th * 64;
        u32 sb = smem_u32(S);

        // A tile: 64x128 f32 -> relu -> bf16 hi/lo (8 float4/thread)
        {
            int row = t >> 2;            // 0..63
            int cb = (t & 3) * 32;
            const float* src = &g_pts[(size_t)(row0 + row) * C_ + cb];
            u32 so = (u32)(row * LDB + cb) * 2;
#pragma unroll
            for (int j = 0; j < 8; ++j) {
                float4 v = *(const float4*)&src[j * 4];
                v.x = fmaxf(v.x, 0.f); v.y = fmaxf(v.y, 0.f);
                v.z = fmaxf(v.z, 0.f); v.w = fmaxf(v.w, 0.f);
                float h0 = bfhi(v.x), h1 = bfhi(v.y), h2 = bfhi(v.z), h3 = bfhi(v.w);
                *(u64*)(S + HA_H + so + j * 8) =
                    (u64)packbf(h0, h1) | ((u64)packbf(h2, h3) << 32);
                *(u64*)(S + HA_L + so + j * 8) =
                    (u64)packbf(v.x - h0, v.y - h1) | ((u64)packbf(v.z - h2, v.w - h3) << 32);
            }
        }
        // W tile: copy precomputed bf16 hi/lo (8 uint4/thread/region)
        {
            int wrow = t >> 1, half = t & 1;
            size_t gb = (size_t)blk * (C_ * C_) + wrow * C_ + half * 64;
            const uint4* wh = (const uint4*)&g_Wsh[gb];
            const uint4* wl = (const uint4*)&g_Wsl[gb];
            u32 wo = (u32)(wrow * LDB + half * 64) * 2;
#pragma unroll
            for (int j = 0; j < 8; ++j) {
                *(uint4*)(S + HW_H + wo + j * 16) = wh[j];
                *(uint4*)(S + HW_L + wo + j * 16) = wl[j];
            }
        }
        __syncthreads();

        int wm = wid & 1, wn = wid >> 1;         // warp tile 32 rows x 32 cols
        int gid = lane >> 2, tig = lane & 3;
        int arow = (lane & 7) + ((lane >> 3) & 1) * 8;
        int acol = ((lane >> 4) & 1) * 8;
        int brow = (lane & 7) + ((lane >> 4) & 1) * 8;
        int bcol = ((lane >> 3) & 1) * 8;

        u32 aAh[2], aAl[2];
#pragma unroll
        for (int mt = 0; mt < 2; ++mt) {
            u32 o = (u32)((wm * 32 + mt * 16 + arow) * LDB + acol) * 2;
            aAh[mt] = sb + HA_H + o;
            aAl[mt] = sb + HA_L + o;
        }
        u32 aBh[2], aBl[2];
#pragma unroll
        for (int p = 0; p < 2; ++p) {
            u32 o = (u32)((wn * 32 + p * 16 + brow) * LDB + bcol) * 2;
            aBh[p] = sb + HW_H + o;
            aBl[p] = sb + HW_L + o;
        }

        float acc[2][4][4];
#pragma unroll
        for (int i = 0; i < 2; ++i)
#pragma unroll
            for (int j = 0; j < 4; ++j)
#pragma unroll
                for (int q = 0; q < 4; ++q) acc[i][j][q] = 0.f;

        for (int kt = 0; kt < 8; ++kt) {
            u32 kadd = kt * 32;
            u32 ah0[4], ah1[4], al0[4], al1[4];
            ldsm_x4(ah0, aAh[0] + kadd); ldsm_x4(ah1, aAh[1] + kadd);
            ldsm_x4(al0, aAl[0] + kadd); ldsm_x4(al1, aAl[1] + kadd);
#pragma unroll
            for (int p = 0; p < 2; ++p) {
                u32 bh[4], bl[4];
                ldsm_x4(bh, aBh[p] + kadd);
                mma16816(acc[0][2 * p],     ah0, bh);
                mma16816(acc[0][2 * p + 1], ah0, bh + 2);
                mma16816(acc[1][2 * p],     ah1, bh);
                mma16816(acc[1][2 * p + 1], ah1, bh + 2);
                mma16816(acc[0][2 * p],     al0, bh);
                mma16816(acc[0][2 * p + 1], al0, bh + 2);
                mma16816(acc[1][2 * p],     al1, bh);
                mma16816(acc[1][2 * p + 1], al1, bh + 2);
                ldsm_x4(bl, aBl[p] + kadd);
                mma16816(acc[0][2 * p],     ah0, bl);
                mma16816(acc[0][2 * p + 1], ah0, bl + 2);
                mma16816(acc[1][2 * p],     ah1, bl);
                mma16816(acc[1][2 * p + 1], ah1, bl + 2);
            }
        }
        // epilogue with fused residual
#pragma unroll
        for (int mt = 0; mt < 2; ++mt) {
#pragma unroll
            for (int nf = 0; nf < 4; ++nf) {
                int r = row0 + wm * 32 + mt * 16 + gid;
                int cc = wn * 32 + nf * 8 + tig * 2;
                const float* a4 = acc[mt][nf];
                float2 p0 = *(const float2*)&g_pts[(size_t)r * C_ + cc];
                float2 p1 = *(const float2*)&g_pts[(size_t)(r + 8) * C_ + cc];
                *(float2*)&g_Ya[(size_t)r * C_ + cc] =
                    make_float2(p0.x + ALPHA_F * a4[0], p0.y + ALPHA_F * a4[1]);
                *(float2*)&g_Ya[(size_t)(r + 8) * C_ + cc] =
                    make_float2(p1.x + ALPHA_F * a4[2], p1.y + ALPHA_F * a4[3]);
            }
        }
    } else {
        // ================= SIMT path: pts@WgT exact fp32 (f32x2), 128-row ====
        float* sAp = (float*)S;                 // [2][16][128]
        float* sWp = (float*)(S + 16384);       // [2][16][128]
#define SA(st, k, m) sAp[(st) * 2048 + (k) * 128 + (m)]
#define SW(st, k, d) sWp[(st) * 2048 + (k) * 128 + (d)]
        const float* A = g_pts;
        int tx = t & 15;            // cols tx*4..+3 and 64+tx*4..+3
        int ty = t >> 4;            // rows ty*8..+7
        int row0 = trip * 128;
        int mA0 = t >> 2, kqA = (t & 3) * 4;

        u64 acc[8][4];
#pragma unroll
        for (int i = 0; i < 8; ++i)
#pragma unroll
            for (int j = 0; j < 4; ++j) acc[i][j] = 0ull;

        // prologue: tile 0 -> stage 0
#pragma unroll
        for (int r = 0; r < 2; ++r) {
            int m = mA0 + r * 64;
            float4 v = *(const float4*)&A[(size_t)(row0 + m) * C_ + kqA];
            SA(0, kqA + 0, m) = v.x; SA(0, kqA + 1, m) = v.y;
            SA(0, kqA + 2, m) = v.z; SA(0, kqA + 3, m) = v.w;
            float4 w = *(const float4*)&Wg[(size_t)m * C_ + kqA];
            SW(0, kqA + 0, m) = w.x; SW(0, kqA + 1, m) = w.y;
            SW(0, kqA + 2, m) = w.z; SW(0, kqA + 3, m) = w.w;
        }
        __syncthreads();

        int stage = 0;
        for (int tt = 0; tt < 8; ++tt) {
            float4 nA[2], nW[2];
            if (tt < 7) {
                int k0n = (tt + 1) * 16;
#pragma unroll
                for (int r = 0; r < 2; ++r) {
                    int m = mA0 + r * 64;
                    nA[r] = *(const float4*)&A[(size_t)(row0 + m) * C_ + k0n + kqA];
                    nW[r] = *(const float4*)&Wg[(size_t)m * C_ + k0n + kqA];
                }
            }
#pragma unroll
            for (int kk = 0; kk < 16; ++kk) {
                float4 af0 = *(const float4*)&SA(stage, kk, ty * 8);
                float4 af1 = *(const float4*)&SA(stage, kk, ty * 8 + 4);
                u64 ap[8] = {dup2(af0.x), dup2(af0.y), dup2(af0.z), dup2(af0.w),
                             dup2(af1.x), dup2(af1.y), dup2(af1.z), dup2(af1.w)};
                ulonglong2 wq0 = *(const ulonglong2*)&SW(stage, kk, tx * 4);
                ulonglong2 wq1 = *(const ulonglong2*)&SW(stage, kk, 64 + tx * 4);
                u64 w[4] = {wq0.x, wq0.y, wq1.x, wq1.y};
#pragma unroll
                for (int i = 0; i < 8; ++i)
#pragma unroll
                    for (int j = 0; j < 4; ++j)
                        ffma2(acc[i][j], ap[i], w[j]);
            }
            if (tt < 7) {
                int ns = stage ^ 1;
#pragma unroll
                for (int r = 0; r < 2; ++r) {
                    int m = mA0 + r * 64;
                    SA(ns, kqA + 0, m) = nA[r].x; SA(ns, kqA + 1, m) = nA[r].y;
                    SA(ns, kqA + 2, m) = nA[r].z; SA(ns, kqA + 3, m) = nA[r].w;
                    SW(ns, kqA + 0, m) = nW[r].x; SW(ns, kqA + 1, m) = nW[r].y;
                    SW(ns, kqA + 2, m) = nW[r].z; SW(ns, kqA + 3, m) = nW[r].w;
                }
                __syncthreads();
                stage = ns;
            }
        }
#pragma unroll
        for (int i = 0; i < 8; ++i) {
            size_t base = (size_t)(row0 + ty * 8 + i) * C_;
            float2 g0 = unpack2(acc[i][0]), g1 = unpack2(acc[i][1]);
            float2 g2 = unpack2(acc[i][2]), g3 = unpack2(acc[i][3]);
            *(float4*)&g_Yg[base + tx * 4]      = make_float4(g0.x, g0.y, g1.x, g1.y);
            *(float4*)&g_Yg[base + 64 + tx * 4] = make_float4(g2.x, g2.y, g3.x, g3.y);
        }
#undef SA
#undef SW
    }
}

// ------- 4) gather + residual: pts = Ya + (1-a)*(adj@Yg) ---------------------
__global__ void gather_combine() {
    int node = blockIdx.x * 8 + (threadIdx.x >> 5);
    int lane = threadIdx.x & 31;
    int base = node & ~(N_ - 1);                  // batch start row
    const int* nb = g_nbr + (size_t)node * KNN;
    int c = lane * 4;
    float4 acc = make_float4(0.f, 0.f, 0.f, 0.f);
#pragma unroll
    for (int s = 0; s < KNN; ++s) {
        const float4 v = *(const float4*)&g_Yg[(size_t)(base + nb[s]) * C_ + c];
        acc.x += v.x; acc.y += v.y; acc.z += v.z; acc.w += v.w;
    }
    float4 ya = *(const float4*)&g_Ya[(size_t)node * C_ + c];
    float4 o;
    o.x = ya.x + ONEMA_F * (WEDGE_F * acc.x);
    o.y = ya.y + ONEMA_F * (WEDGE_F * acc.y);
    o.z = ya.z + ONEMA_F * (WEDGE_F * acc.z);
    o.w = ya.w + ONEMA_F * (WEDGE_F * acc.w);
    *(float4*)&g_pts[(size_t)node * C_ + c] = o;
}

// ------- 5) unpool projection: Uc = pts@WucT, Ug = pts@WugT (6 outs each) ----
__global__ void unpool_proj(const float* __restrict__ Wuc,
                            const float* __restrict__ Wug) {
    __shared__ float swc[6 * C_], swg[6 * C_];
    for (int i = threadIdx.x; i < 6 * C_; i += 256) { swc[i] = Wuc[i]; swg[i] = Wug[i]; }
    __syncthreads();
    int node = blockIdx.x * 8 + (threadIdx.x >> 5);
    int lane = threadIdx.x & 31;
    float4 p = *(const float4*)&g_pts[(size_t)node * C_ + lane * 4];
#pragma unroll
    for (int o = 0; o < 6; ++o) {
        float4 wc = *(const float4*)&swc[o * C_ + lane * 4];
        float4 wg = *(const float4*)&swg[o * C_ + lane * 4];
        float dc = p.x * wc.x + p.y * wc.y + p.z * wc.z + p.w * wc.w;
        float dg = p.x * wg.x + p.y * wg.y + p.z * wg.z + p.w * wg.w;
#pragma unroll
        for (int off = 16; off; off >>= 1) {
            dc += __shfl_xor_sync(0xffffffffu, dc, off);
            dg += __shfl_xor_sync(0xffffffffu, dg, off);
        }
        if (lane == 0) {
            g_Uc[(size_t)node * 6 + o] = dc;
            g_Ug[(size_t)node * 6 + o] = dg;
        }
    }
}

// ------- 6) finalize new_xyz: a*Uc + (1-a)*(adj@Ug), fold + reshape ----------
__global__ void finalize_xyz(const float* __restrict__ xyz, float* __restrict__ out) {
    int node = blockIdx.x * 256 + threadIdx.x;        // 0..32767
    int b = node >> 11, n = node & (N_ - 1);
    int base = node & ~(N_ - 1);
    const int* nb = g_nbr + (size_t)node * KNN;
    float g[6] = {0.f, 0.f, 0.f, 0.f, 0.f, 0.f};
#pragma unroll
    for (int s = 0; s < KNN; ++s) {
        const float* r = g_Ug + (size_t)(base + nb[s]) * 6;
#pragma unroll
        for (int o = 0; o < 6; ++o) g[o] += r[o];
    }
#pragma unroll
    for (int o = 0; o < 6; ++o) {
        float v = ALPHA_F * g_Uc[(size_t)node * 6 + o] + ONEMA_F * (WEDGE_F * g[o]);
        int cdim = o >> 1, t = o & 1;
        out[(size_t)b * 3 * (2 * N_) + cdim * (2 * N_) + t * N_ + n] =
            v + xyz[(size_t)b * 3 * N_ + cdim * N_ + n];
    }
}

// ------- 7) transpose pts (B,N,C) -> output (B,C,N) --------------------------
__global__ void transpose_out(float* __restrict__ out) {
    __shared__ float tile[32][33];
    int b = blockIdx.z;
    int n0 = blockIdx.x * 32, c0 = blockIdx.y * 32;
    const float* src = g_pts + (size_t)b * N_ * C_;
    float* dst = out + (size_t)b * C_ * N_;
    for (int r = threadIdx.y; r < 32; r += 8)
        tile[r][threadIdx.x] = src[(n0 + r) * C_ + c0 + threadIdx.x];
    __syncthreads();
    for (int r = threadIdx.y; r < 32; r += 8)
        dst[(c0 + r) * N_ + n0 + threadIdx.x] = tile[threadIdx.x][r];
}

// -----------------------------------------------------------------------------
extern "C" void kernel_launch(void* const* d_in, const int* in_sizes, int n_in,
                              void* d_out, int out_size) {
    const float* xyz    = (const float*)d_in[0];   // (16,3,2048)
    const float* points = (const float*)d_in[1];   // (16,128,2048)
    const float* Wc     = (const float*)d_in[2];   // (4,128,128)
    const float* Wg     = (const float*)d_in[3];   // (4,128,128)
    const float* Wuc    = (const float*)d_in[4];   // (6,128)
    const float* Wug    = (const float*)d_in[5];   // (6,128)
    float* out = (float*)d_out;                    // [new_xyz | pts_T] concatenated
    (void)in_sizes; (void)n_in; (void)out_size;

    // host-side config (idempotent; not a stream op)
    cudaFuncSetAttribute(gemm_hybrid, cudaFuncAttributeMaxDynamicSharedMemorySize,
                         GEMM_SMEM);

    // launch order: ncu (-s 5 -c 1) lands on a gemm_hybrid launch
    knn_kernel<<<B_ * 8, 256>>>(xyz, Wc);                                    // 1
    transpose_in<<<dim3(N_ / 32, C_ / 32, B_ / 2), dim3(32, 8)>>>(points, 0);       // 2
    transpose_in<<<dim3(N_ / 32, C_ / 32, B_ / 2), dim3(32, 8)>>>(points, B_ / 2);  // 3
    for (int i = 0; i < NBLK; ++i) {
        gemm_hybrid<<<768, 256, GEMM_SMEM>>>(Wg + (size_t)i * C_ * C_, i);   // 4,6,8,10
        gather_combine<<<M_ / 8, 256>>>();                                   // 5,7,9,11
    }
    unpool_proj<<<M_ / 8, 256>>>(Wuc, Wug);
    finalize_xyz<<<M_ / 256, 256>>>(xyz, out);
    transpose_out<<<dim3(N_ / 32, C_ / 32, B_), dim3(32, 8)>>>(out + (size_t)B_ * 3 * 2 * N_);
}

// round 11
// speedup vs baseline: 1.0117x; 1.0117x over previous
#include <cuda_runtime.h>
#include <cuda_bf16.h>
#include <float.h>

// Problem constants
#define B_   16
#define N_   2048
#define C_   128
#define M_   (B_ * N_)          // 32768 rows
#define KNN  8
#define NBLK 4

#define ALPHA_F    0.8888888888888888f   // 8/9
#define ONEMA_F    0.1111111111111111f   // 1/9
#define WEDGE_F    0.125f                // normalized adjacency entry (deg=8 everywhere)

typedef unsigned long long u64;
typedef unsigned int u32;

// ---------------- scratch (static device globals; no allocs allowed) ---------
__device__ float g_pts[M_ * C_];
__device__ float g_Ya [M_ * C_];   // epilogue-fused: pts + alpha * relu(pts)@WcT
__device__ float g_Yg [M_ * C_];
__device__ float g_Uc [M_ * 6];
__device__ float g_Ug [M_ * 6];
__device__ int   g_nbr[M_ * KNN];  // [0]=self, [1..7]=kNN (within-batch indices)
// precomputed bf16 splits of Wc/Wg: [mat][blk][128*128]
__device__ __nv_bfloat16 g_Wsh[2 * NBLK * C_ * C_];
__device__ __nv_bfloat16 g_Wsl[2 * NBLK * C_ * C_];

// ======================= helpers =============================================
__device__ __forceinline__ u32 smem_u32(const void* p) {
    u32 a;
    asm("{ .reg .u64 t; cvta.to.shared.u64 t, %1; cvt.u32.u64 %0, t; }"
        : "=r"(a) : "l"(p));
    return a;
}
__device__ __forceinline__ float bfhi(float x) {
    return __bfloat162float(__float2bfloat16_rn(x));
}
__device__ __forceinline__ u32 packbf(float lo, float hi) {
    u32 r; asm("cvt.rn.bf16x2.f32 %0, %1, %2;" : "=r"(r) : "f"(hi), "f"(lo));
    return r;
}
__device__ __forceinline__ void ldsm_x4(u32 r[4], u32 addr) {
    asm volatile("ldmatrix.sync.aligned.m8n8.x4.shared.b16 {%0,%1,%2,%3}, [%4];"
        : "=r"(r[0]), "=r"(r[1]), "=r"(r[2]), "=r"(r[3]) : "r"(addr));
}
__device__ __forceinline__ void mma16816(float c[4], const u32 a[4], const u32 b[2]) {
    asm volatile("mma.sync.aligned.m16n8k16.row.col.f32.bf16.bf16.f32 "
        "{%0,%1,%2,%3}, {%4,%5,%6,%7}, {%8,%9}, {%0,%1,%2,%3};"
        : "+f"(c[0]), "+f"(c[1]), "+f"(c[2]), "+f"(c[3])
        : "r"(a[0]), "r"(a[1]), "r"(a[2]), "r"(a[3]), "r"(b[0]), "r"(b[1]));
}

// HMMA smem layout (bf16, padded stride 136; 64-row A tile, 128-row W tile)
#define LDB  136
#define HA_H 0
#define HA_L 17408
#define HW_H 34816
#define HW_L 69632
#define GEMM_SMEM 104448        // 2 CTAs/SM (209KB < 228KB)

// ---------------- 1) kNN top-8 + W bf16 split prep ---------------------------
__global__ void knn_kernel(const float* __restrict__ xyz,
                           const float* __restrict__ Wc,
                           const float* __restrict__ Wg) {
    __shared__ float4 sP[N_];   // (x, y, z, |p|^2) interleaved -> 1 LDS.128/cand
    // fold-in: precompute Wc/Wg hi/lo bf16 splits (4 elems/thread)
    {
        int gt = blockIdx.x * 256 + threadIdx.x;
        for (int i = gt; i < NBLK * C_ * C_; i += 128 * 256) {
            float w = Wc[i];
            float h = bfhi(w);
            g_Wsh[i] = __float2bfloat16_rn(h);
            g_Wsl[i] = __float2bfloat16_rn(w - h);
            float w2 = Wg[i];
            float h2 = bfhi(w2);
            g_Wsh[NBLK * C_ * C_ + i] = __float2bfloat16_rn(h2);
            g_Wsl[NBLK * C_ * C_ + i] = __float2bfloat16_rn(w2 - h2);
        }
    }
    int b = blockIdx.x >> 3;
    int qBase = (blockIdx.x & 7) * 256;
    const float* X = xyz + (size_t)b * 3 * N_;
    for (int i = threadIdx.x; i < N_; i += 256) {
        float x = X[i], y = X[N_ + i], z = X[2 * N_ + i];
        sP[i] = make_float4(x, y, z, x * x + y * y + z * z);
    }
    __syncthreads();

    int q = qBase + threadIdx.x;
    float4 qp = sP[q];
    float bd[KNN]; int bi[KNN];
#pragma unroll
    for (int s = 0; s < KNN; ++s) { bd[s] = FLT_MAX; bi[s] = 0x7fffffff; }

    for (int j = 0; j < N_; ++j) {
        float4 pj = sP[j];
        float inner = qp.x * pj.x + qp.y * pj.y + qp.z * pj.z;
        float d = (qp.w + pj.w) - 2.0f * inner;
        if (d < bd[KNN - 1]) {                   // strict <: stable tie (lower idx wins)
            bd[KNN - 1] = d; bi[KNN - 1] = j;
#pragma unroll
            for (int s = KNN - 1; s > 0; --s) {
                if (bd[s] < bd[s - 1]) {
                    float td = bd[s]; bd[s] = bd[s - 1]; bd[s - 1] = td;
                    int   ti = bi[s]; bi[s] = bi[s - 1]; bi[s - 1] = ti;
                }
            }
        }
    }
    int* outp = g_nbr + (size_t)(b * N_ + q) * KNN;
    outp[0] = q;
#pragma unroll
    for (int s = 1; s < KNN; ++s) outp[s] = bi[s];
}

// ------- 2) transpose points (B,C,N) -> pts (B,N,C), half the batch per call -
__global__ void transpose_in(const float* __restrict__ pin, int bOff) {
    __shared__ float tile[32][33];
    int b = blockIdx.z + bOff;
    int n0 = blockIdx.x * 32, c0 = blockIdx.y * 32;
    const float* src = pin + (size_t)b * C_ * N_;
    float* dst = g_pts + (size_t)b * N_ * C_;
    for (int r = threadIdx.y; r < 32; r += 8)
        tile[r][threadIdx.x] = src[(c0 + r) * N_ + n0 + threadIdx.x];
    __syncthreads();
    for (int r = threadIdx.y; r < 32; r += 8)
        dst[(n0 + r) * C_ + c0 + threadIdx.x] = tile[threadIdx.x][r];
}

// ---------------- 3) HMMA GEMM (mma.sync bf16 3-split), 64-row tiles ---------
// grid (512, 2). y=0: Ya = pts + ALPHA*(relu(pts)@WcT); y=1: Yg = pts@WgT.
// 104.4KB smem -> 2 CTAs/SM (16 warps) for latency hiding.
// 8 warps as 2x4: warp (wm=wid&1, wn=wid>>1) owns rows wm*32..+31, cols wn*32..+31.
__global__ __launch_bounds__(256, 2) void gemm_tc(int blk) {
    extern __shared__ char S[];
    int t = threadIdx.x;
    int wid = t >> 5, lane = t & 31;
    const int mat = blockIdx.y;               // 0 = Wc/relu path, 1 = Wg
    const bool doRelu = (mat == 0);
    int row0 = blockIdx.x * 64;
    u32 sb = smem_u32(S);

    // A tile: 64x128 f32 -> (relu) -> bf16 hi/lo (8 float4/thread)
    {
        int row = t >> 2;            // 0..63
        int cb = (t & 3) * 32;
        const float* src = &g_pts[(size_t)(row0 + row) * C_ + cb];
        u32 so = (u32)(row * LDB + cb) * 2;
#pragma unroll
        for (int j = 0; j < 8; ++j) {
            float4 v = *(const float4*)&src[j * 4];
            if (doRelu) {
                v.x = fmaxf(v.x, 0.f); v.y = fmaxf(v.y, 0.f);
                v.z = fmaxf(v.z, 0.f); v.w = fmaxf(v.w, 0.f);
            }
            float h0 = bfhi(v.x), h1 = bfhi(v.y), h2 = bfhi(v.z), h3 = bfhi(v.w);
            *(u64*)(S + HA_H + so + j * 8) =
                (u64)packbf(h0, h1) | ((u64)packbf(h2, h3) << 32);
            *(u64*)(S + HA_L + so + j * 8) =
                (u64)packbf(v.x - h0, v.y - h1) | ((u64)packbf(v.z - h2, v.w - h3) << 32);
        }
    }
    // W tile: copy precomputed bf16 hi/lo (8 uint4/thread/region)
    {
        int wrow = t >> 1, half = t & 1;
        size_t gb = (size_t)(mat * NBLK + blk) * (C_ * C_) + wrow * C_ + half * 64;
        const uint4* wh = (const uint4*)&g_Wsh[gb];
        const uint4* wl = (const uint4*)&g_Wsl[gb];
        u32 wo = (u32)(wrow * LDB + half * 64) * 2;
#pragma unroll
        for (int j = 0; j < 8; ++j) {
            *(uint4*)(S + HW_H + wo + j * 16) = wh[j];
            *(uint4*)(S + HW_L + wo + j * 16) = wl[j];
        }
    }
    __syncthreads();

    int wm = wid & 1, wn = wid >> 1;         // warp tile 32 rows x 32 cols
    int gid = lane >> 2, tig = lane & 3;
    int arow = (lane & 7) + ((lane >> 3) & 1) * 8;
    int acol = ((lane >> 4) & 1) * 8;
    int brow = (lane & 7) + ((lane >> 4) & 1) * 8;
    int bcol = ((lane >> 3) & 1) * 8;

    u32 aAh[2], aAl[2];
#pragma unroll
    for (int mt = 0; mt < 2; ++mt) {
        u32 o = (u32)((wm * 32 + mt * 16 + arow) * LDB + acol) * 2;
        aAh[mt] = sb + HA_H + o;
        aAl[mt] = sb + HA_L + o;
    }
    u32 aBh[2], aBl[2];
#pragma unroll
    for (int p = 0; p < 2; ++p) {
        u32 o = (u32)((wn * 32 + p * 16 + brow) * LDB + bcol) * 2;
        aBh[p] = sb + HW_H + o;
        aBl[p] = sb + HW_L + o;
    }

    float acc[2][4][4];
#pragma unroll
    for (int i = 0; i < 2; ++i)
#pragma unroll
        for (int j = 0; j < 4; ++j)
#pragma unroll
            for (int q = 0; q < 4; ++q) acc[i][j][q] = 0.f;

    for (int kt = 0; kt < 8; ++kt) {
        u32 kadd = kt * 32;
        u32 ah0[4], ah1[4], al0[4], al1[4];
        ldsm_x4(ah0, aAh[0] + kadd); ldsm_x4(ah1, aAh[1] + kadd);
        ldsm_x4(al0, aAl[0] + kadd); ldsm_x4(al1, aAl[1] + kadd);
#pragma unroll
        for (int p = 0; p < 2; ++p) {
            u32 bh[4], bl[4];
            ldsm_x4(bh, aBh[p] + kadd);
            mma16816(acc[0][2 * p],     ah0, bh);
            mma16816(acc[0][2 * p + 1], ah0, bh + 2);
            mma16816(acc[1][2 * p],     ah1, bh);
            mma16816(acc[1][2 * p + 1], ah1, bh + 2);
            mma16816(acc[0][2 * p],     al0, bh);
            mma16816(acc[0][2 * p + 1], al0, bh + 2);
            mma16816(acc[1][2 * p],     al1, bh);
            mma16816(acc[1][2 * p + 1], al1, bh + 2);
            ldsm_x4(bl, aBl[p] + kadd);
            mma16816(acc[0][2 * p],     ah0, bl);
            mma16816(acc[0][2 * p + 1], ah0, bl + 2);
            mma16816(acc[1][2 * p],     ah1, bl);
            mma16816(acc[1][2 * p + 1], ah1, bl + 2);
        }
    }

    // epilogue: c0,c1 -> (row, col..+1); c2,c3 -> (row+8, col..+1)
#pragma unroll
    for (int mt = 0; mt < 2; ++mt) {
#pragma unroll
        for (int nf = 0; nf < 4; ++nf) {
            int r = row0 + wm * 32 + mt * 16 + gid;
            int cc = wn * 32 + nf * 8 + tig * 2;
            const float* a4 = acc[mt][nf];
            if (doRelu) {
                float2 p0 = *(const float2*)&g_pts[(size_t)r * C_ + cc];
                float2 p1 = *(const float2*)&g_pts[(size_t)(r + 8) * C_ + cc];
                *(float2*)&g_Ya[(size_t)r * C_ + cc] =
                    make_float2(p0.x + ALPHA_F * a4[0], p0.y + ALPHA_F * a4[1]);
                *(float2*)&g_Ya[(size_t)(r + 8) * C_ + cc] =
                    make_float2(p1.x + ALPHA_F * a4[2], p1.y + ALPHA_F * a4[3]);
            } else {
                *(float2*)&g_Yg[(size_t)r * C_ + cc]       = make_float2(a4[0], a4[1]);
                *(float2*)&g_Yg[(size_t)(r + 8) * C_ + cc] = make_float2(a4[2], a4[3]);
            }
        }
    }
}

// ------- 4) gather + residual: pts = Ya + (1-a)*(adj@Yg) ---------------------
__global__ void gather_combine() {
    int node = blockIdx.x * 8 + (threadIdx.x >> 5);
    int lane = threadIdx.x & 31;
    int base = node & ~(N_ - 1);                  // batch start row
    const int* nb = g_nbr + (size_t)node * KNN;
    int c = lane * 4;
    float4 acc = make_float4(0.f, 0.f, 0.f, 0.f);
#pragma unroll
    for (int s = 0; s < KNN; ++s) {
        const float4 v = *(const float4*)&g_Yg[(size_t)(base + nb[s]) * C_ + c];
        acc.x += v.x; acc.y += v.y; acc.z += v.z; acc.w += v.w;
    }
    float4 ya = *(const float4*)&g_Ya[(size_t)node * C_ + c];
    float4 o;
    o.x = ya.x + ONEMA_F * (WEDGE_F * acc.x);
    o.y = ya.y + ONEMA_F * (WEDGE_F * acc.y);
    o.z = ya.z + ONEMA_F * (WEDGE_F * acc.z);
    o.w = ya.w + ONEMA_F * (WEDGE_F * acc.w);
    *(float4*)&g_pts[(size_t)node * C_ + c] = o;
}

// ------- 5) unpool projection: Uc = pts@WucT, Ug = pts@WugT (6 outs each) ----
__global__ void unpool_proj(const float* __restrict__ Wuc,
                            const float* __restrict__ Wug) {
    __shared__ float swc[6 * C_], swg[6 * C_];
    for (int i = threadIdx.x; i < 6 * C_; i += 256) { swc[i] = Wuc[i]; swg[i] = Wug[i]; }
    __syncthreads();
    int node = blockIdx.x * 8 + (threadIdx.x >> 5);
    int lane = threadIdx.x & 31;
    float4 p = *(const float4*)&g_pts[(size_t)node * C_ + lane * 4];
#pragma unroll
    for (int o = 0; o < 6; ++o) {
        float4 wc = *(const float4*)&swc[o * C_ + lane * 4];
        float4 wg = *(const float4*)&swg[o * C_ + lane * 4];
        float dc = p.x * wc.x + p.y * wc.y + p.z * wc.z + p.w * wc.w;
        float dg = p.x * wg.x + p.y * wg.y + p.z * wg.z + p.w * wg.w;
#pragma unroll
        for (int off = 16; off; off >>= 1) {
            dc += __shfl_xor_sync(0xffffffffu, dc, off);
            dg += __shfl_xor_sync(0xffffffffu, dg, off);
        }
        if (lane == 0) {
            g_Uc[(size_t)node * 6 + o] = dc;
            g_Ug[(size_t)node * 6 + o] = dg;
        }
    }
}

// ------- 6) finalize new_xyz: a*Uc + (1-a)*(adj@Ug), fold + reshape ----------
__global__ void finalize_xyz(const float* __restrict__ xyz, float* __restrict__ out) {
    int node = blockIdx.x * 256 + threadIdx.x;        // 0..32767
    int b = node >> 11, n = node & (N_ - 1);
    int base = node & ~(N_ - 1);
    const int* nb = g_nbr + (size_t)node * KNN;
    float g[6] = {0.f, 0.f, 0.f, 0.f, 0.f, 0.f};
#pragma unroll
    for (int s = 0; s < KNN; ++s) {
        const float* r = g_Ug + (size_t)(base + nb[s]) * 6;
#pragma unroll
        for (int o = 0; o < 6; ++o) g[o] += r[o];
    }
#pragma unroll
    for (int o = 0; o < 6; ++o) {
        float v = ALPHA_F * g_Uc[(size_t)node * 6 + o] + ONEMA_F * (WEDGE_F * g[o]);
        int cdim = o >> 1, t = o & 1;
        out[(size_t)b * 3 * (2 * N_) + cdim * (2 * N_) + t * N_ + n] =
            v + xyz[(size_t)b * 3 * N_ + cdim * N_ + n];
    }
}

// ------- 7) transpose pts (B,N,C) -> output (B,C,N) --------------------------
__global__ void transpose_out(float* __restrict__ out) {
    __shared__ float tile[32][33];
    int b = blockIdx.z;
    int n0 = blockIdx.x * 32, c0 = blockIdx.y * 32;
    const float* src = g_pts + (size_t)b * N_ * C_;
    float* dst = out + (size_t)b * C_ * N_;
    for (int r = threadIdx.y; r < 32; r += 8)
        tile[r][threadIdx.x] = src[(n0 + r) * C_ + c0 + threadIdx.x];
    __syncthreads();
    for (int r = threadIdx.y; r < 32; r += 8)
        dst[(c0 + r) * N_ + n0 + threadIdx.x] = tile[threadIdx.x][r];
}

// -----------------------------------------------------------------------------
extern "C" void kernel_launch(void* const* d_in, const int* in_sizes, int n_in,
                              void* d_out, int out_size) {
    const float* xyz    = (const float*)d_in[0];   // (16,3,2048)
    const float* points = (const float*)d_in[1];   // (16,128,2048)
    const float* Wc     = (const float*)d_in[2];   // (4,128,128)
    const float* Wg     = (const float*)d_in[3];   // (4,128,128)
    const float* Wuc    = (const float*)d_in[4];   // (6,128)
    const float* Wug    = (const float*)d_in[5];   // (6,128)
    float* out = (float*)d_out;                    // [new_xyz | pts_T] concatenated
    (void)in_sizes; (void)n_in; (void)out_size;

    // host-side config (idempotent; not a stream op)
    cudaFuncSetAttribute(gemm_tc, cudaFuncAttributeMaxDynamicSharedMemorySize,
                         GEMM_SMEM);

    // launch order: ncu (-s 5 -c 1) lands on a gemm_tc launch (idx 5)
    knn_kernel<<<B_ * 8, 256>>>(xyz, Wc, Wg);                                // 0
    transpose_in<<<dim3(N_ / 32, C_ / 32, B_ / 2), dim3(32, 8)>>>(points, 0);       // 1
    transpose_in<<<dim3(N_ / 32, C_ / 32, B_ / 2), dim3(32, 8)>>>(points, B_ / 2);  // 2
    for (int i = 0; i < NBLK; ++i) {
        gemm_tc<<<dim3(M_ / 64, 2), 256, GEMM_SMEM>>>(i);                    // 3,5,7,9
        gather_combine<<<M_ / 8, 256>>>();                                   // 4,6,8,10
    }
    unpool_proj<<<M_ / 8, 256>>>(Wuc, Wug);
    finalize_xyz<<<M_ / 256, 256>>>(xyz, out);
    transpose_out<<<dim3(N_ / 32, C_ / 32, B_), dim3(32, 8)>>>(out + (size_t)B_ * 3 * 2 * N_);
}

// round 12
// speedup vs baseline: 1.0175x; 1.0058x over previous
#include <cuda_runtime.h>
#include <cuda_bf16.h>
#include <float.h>

// Problem constants
#define B_   16
#define N_   2048
#define C_   128
#define M_   (B_ * N_)          // 32768 rows
#define KNN  8
#define NBLK 4

#define ALPHA_F    0.8888888888888888f   // 8/9
#define ONEMA_F    0.1111111111111111f   // 1/9
#define WEDGE_F    0.125f                // normalized adjacency entry (deg=8 everywhere)

typedef unsigned long long u64;
typedef unsigned int u32;

// ---------------- scratch (static device globals; no allocs allowed) ---------
__device__ float g_pts[M_ * C_];
__device__ float g_Ya [M_ * C_];   // epilogue-fused: pts + alpha * relu(pts)@WcT
__device__ float g_Yg [M_ * C_];
__device__ float g_Uc [M_ * 6];
__device__ float g_Ug [M_ * 6];
__device__ int   g_nbr[M_ * KNN];  // [0]=self, [1..7]=kNN (within-batch indices)
// precomputed bf16 splits of Wc (HMMA path): [blk][128*128]
__device__ __nv_bfloat16 g_Wsh[NBLK * C_ * C_];
__device__ __nv_bfloat16 g_Wsl[NBLK * C_ * C_];

// ======================= helpers =============================================
__device__ __forceinline__ u32 smem_u32(const void* p) {
    u32 a;
    asm("{ .reg .u64 t; cvta.to.shared.u64 t, %1; cvt.u32.u64 %0, t; }"
        : "=r"(a) : "l"(p));
    return a;
}
__device__ __forceinline__ float bfhi(float x) {
    return __bfloat162float(__float2bfloat16_rn(x));
}
__device__ __forceinline__ u32 packbf(float lo, float hi) {
    u32 r; asm("cvt.rn.bf16x2.f32 %0, %1, %2;" : "=r"(r) : "f"(hi), "f"(lo));
    return r;
}
__device__ __forceinline__ void ldsm_x4(u32 r[4], u32 addr) {
    asm volatile("ldmatrix.sync.aligned.m8n8.x4.shared.b16 {%0,%1,%2,%3}, [%4];"
        : "=r"(r[0]), "=r"(r[1]), "=r"(r[2]), "=r"(r[3]) : "r"(addr));
}
__device__ __forceinline__ void mma16816(float c[4], const u32 a[4], const u32 b[2]) {
    asm volatile("mma.sync.aligned.m16n8k16.row.col.f32.bf16.bf16.f32 "
        "{%0,%1,%2,%3}, {%4,%5,%6,%7}, {%8,%9}, {%0,%1,%2,%3};"
        : "+f"(c[0]), "+f"(c[1]), "+f"(c[2]), "+f"(c[3])
        : "r"(a[0]), "r"(a[1]), "r"(a[2]), "r"(a[3]), "r"(b[0]), "r"(b[1]));
}
__device__ __forceinline__ void ffma2(u64 &acc, u64 a, u64 b) {
    asm("fma.rn.f32x2 %0, %1, %2, %0;" : "+l"(acc) : "l"(a), "l"(b));
}
__device__ __forceinline__ float2 unpack2(u64 v) {
    float2 f; asm("mov.b64 {%0, %1}, %2;" : "=f"(f.x), "=f"(f.y) : "l"(v)); return f;
}
__device__ __forceinline__ u64 dup2(float a) {
    u64 r; asm("mov.b64 %0, {%1, %1};" : "=l"(r) : "f"(a)); return r;
}

// HMMA smem layout (bf16, padded stride 136; 64-row A tile, 128-row W tile)
#define LDB  136
#define HA_H 0
#define HA_L 17408
#define HW_H 34816
#define HW_L 69632
#define GEMM_SMEM 104448

// ---------------- 1) kNN top-8 + Wc bf16 split prep --------------------------
__global__ void knn_kernel(const float* __restrict__ xyz,
                           const float* __restrict__ Wc) {
    __shared__ float4 sP[N_];   // (x, y, z, |p|^2) interleaved -> 1 LDS.128/cand
    {
        int gt = blockIdx.x * 256 + threadIdx.x;
        for (int i = gt; i < NBLK * C_ * C_; i += 128 * 256) {
            float w = Wc[i];
            float h = bfhi(w);
            g_Wsh[i] = __float2bfloat16_rn(h);
            g_Wsl[i] = __float2bfloat16_rn(w - h);
        }
    }
    int b = blockIdx.x >> 3;
    int qBase = (blockIdx.x & 7) * 256;
    const float* X = xyz + (size_t)b * 3 * N_;
    for (int i = threadIdx.x; i < N_; i += 256) {
        float x = X[i], y = X[N_ + i], z = X[2 * N_ + i];
        sP[i] = make_float4(x, y, z, x * x + y * y + z * z);
    }
    __syncthreads();

    int q = qBase + threadIdx.x;
    float4 qp = sP[q];
    float bd[KNN]; int bi[KNN];
#pragma unroll
    for (int s = 0; s < KNN; ++s) { bd[s] = FLT_MAX; bi[s] = 0x7fffffff; }

    for (int j = 0; j < N_; ++j) {
        float4 pj = sP[j];
        float inner = qp.x * pj.x + qp.y * pj.y + qp.z * pj.z;
        float d = (qp.w + pj.w) - 2.0f * inner;
        if (d < bd[KNN - 1]) {                   // strict <: stable tie (lower idx wins)
            bd[KNN - 1] = d; bi[KNN - 1] = j;
#pragma unroll
            for (int s = KNN - 1; s > 0; --s) {
                if (bd[s] < bd[s - 1]) {
                    float td = bd[s]; bd[s] = bd[s - 1]; bd[s - 1] = td;
                    int   ti = bi[s]; bi[s] = bi[s - 1]; bi[s - 1] = ti;
                }
            }
        }
    }
    int* outp = g_nbr + (size_t)(b * N_ + q) * KNN;
    outp[0] = q;
#pragma unroll
    for (int s = 1; s < KNN; ++s) outp[s] = bi[s];
}

// ------- 2) transpose points (B,C,N) -> pts (B,N,C) --------------------------
__global__ void transpose_in(const float* __restrict__ pin) {
    __shared__ float tile[32][33];
    int b = blockIdx.z;
    int n0 = blockIdx.x * 32, c0 = blockIdx.y * 32;
    const float* src = pin + (size_t)b * C_ * N_;
    float* dst = g_pts + (size_t)b * N_ * C_;
    for (int r = threadIdx.y; r < 32; r += 8)
        tile[r][threadIdx.x] = src[(c0 + r) * N_ + n0 + threadIdx.x];
    __syncthreads();
    for (int r = threadIdx.y; r < 32; r += 8)
        dst[(n0 + r) * C_ + c0 + threadIdx.x] = tile[threadIdx.x][r];
}

// ---------------- 3a) HMMA kernel: Ya = pts + ALPHA*(relu(pts)@WcT) ----------
// 512 CTAs x 64-row tiles, bf16 3-split (hh+lh+hl) on the tensor pipe.
__global__ __launch_bounds__(256, 2) void gemm_ya(int blk) {
    extern __shared__ char S[];
    int t = threadIdx.x;
    int wid = t >> 5, lane = t & 31;
    int row0 = blockIdx.x * 64;
    u32 sb = smem_u32(S);

    // A tile: 64x128 f32 -> relu -> bf16 hi/lo (8 float4/thread)
    {
        int row = t >> 2;
        int cb = (t & 3) * 32;
        const float* src = &g_pts[(size_t)(row0 + row) * C_ + cb];
        u32 so = (u32)(row * LDB + cb) * 2;
#pragma unroll
        for (int j = 0; j < 8; ++j) {
            float4 v = *(const float4*)&src[j * 4];
            v.x = fmaxf(v.x, 0.f); v.y = fmaxf(v.y, 0.f);
            v.z = fmaxf(v.z, 0.f); v.w = fmaxf(v.w, 0.f);
            float h0 = bfhi(v.x), h1 = bfhi(v.y), h2 = bfhi(v.z), h3 = bfhi(v.w);
            *(u64*)(S + HA_H + so + j * 8) =
                (u64)packbf(h0, h1) | ((u64)packbf(h2, h3) << 32);
            *(u64*)(S + HA_L + so + j * 8) =
                (u64)packbf(v.x - h0, v.y - h1) | ((u64)packbf(v.z - h2, v.w - h3) << 32);
        }
    }
    // W tile: precomputed bf16 hi/lo
    {
        int wrow = t >> 1, half = t & 1;
        size_t gb = (size_t)blk * (C_ * C_) + wrow * C_ + half * 64;
        const uint4* wh = (const uint4*)&g_Wsh[gb];
        const uint4* wl = (const uint4*)&g_Wsl[gb];
        u32 wo = (u32)(wrow * LDB + half * 64) * 2;
#pragma unroll
        for (int j = 0; j < 8; ++j) {
            *(uint4*)(S + HW_H + wo + j * 16) = wh[j];
            *(uint4*)(S + HW_L + wo + j * 16) = wl[j];
        }
    }
    __syncthreads();

    int wm = wid & 1, wn = wid >> 1;         // warp tile 32 rows x 32 cols
    int gid = lane >> 2, tig = lane & 3;
    int arow = (lane & 7) + ((lane >> 3) & 1) * 8;
    int acol = ((lane >> 4) & 1) * 8;
    int brow = (lane & 7) + ((lane >> 4) & 1) * 8;
    int bcol = ((lane >> 3) & 1) * 8;

    u32 aAh[2], aAl[2];
#pragma unroll
    for (int mt = 0; mt < 2; ++mt) {
        u32 o = (u32)((wm * 32 + mt * 16 + arow) * LDB + acol) * 2;
        aAh[mt] = sb + HA_H + o;
        aAl[mt] = sb + HA_L + o;
    }
    u32 aBh[2], aBl[2];
#pragma unroll
    for (int p = 0; p < 2; ++p) {
        u32 o = (u32)((wn * 32 + p * 16 + brow) * LDB + bcol) * 2;
        aBh[p] = sb + HW_H + o;
        aBl[p] = sb + HW_L + o;
    }

    float acc[2][4][4];
#pragma unroll
    for (int i = 0; i < 2; ++i)
#pragma unroll
        for (int j = 0; j < 4; ++j)
#pragma unroll
            for (int q = 0; q < 4; ++q) acc[i][j][q] = 0.f;

    for (int kt = 0; kt < 8; ++kt) {
        u32 kadd = kt * 32;
        u32 ah0[4], ah1[4], al0[4], al1[4];
        ldsm_x4(ah0, aAh[0] + kadd); ldsm_x4(ah1, aAh[1] + kadd);
        ldsm_x4(al0, aAl[0] + kadd); ldsm_x4(al1, aAl[1] + kadd);
#pragma unroll
        for (int p = 0; p < 2; ++p) {
            u32 bh[4], bl[4];
            ldsm_x4(bh, aBh[p] + kadd);
            mma16816(acc[0][2 * p],     ah0, bh);
            mma16816(acc[0][2 * p + 1], ah0, bh + 2);
            mma16816(acc[1][2 * p],     ah1, bh);
            mma16816(acc[1][2 * p + 1], ah1, bh + 2);
            mma16816(acc[0][2 * p],     al0, bh);
            mma16816(acc[0][2 * p + 1], al0, bh + 2);
            mma16816(acc[1][2 * p],     al1, bh);
            mma16816(acc[1][2 * p + 1], al1, bh + 2);
            ldsm_x4(bl, aBl[p] + kadd);
            mma16816(acc[0][2 * p],     ah0, bl);
            mma16816(acc[0][2 * p + 1], ah0, bl + 2);
            mma16816(acc[1][2 * p],     ah1, bl);
            mma16816(acc[1][2 * p + 1], ah1, bl + 2);
        }
    }

    // epilogue with fused residual
#pragma unroll
    for (int mt = 0; mt < 2; ++mt) {
#pragma unroll
        for (int nf = 0; nf < 4; ++nf) {
            int r = row0 + wm * 32 + mt * 16 + gid;
            int cc = wn * 32 + nf * 8 + tig * 2;
            const float* a4 = acc[mt][nf];
            float2 p0 = *(const float2*)&g_pts[(size_t)r * C_ + cc];
            float2 p1 = *(const float2*)&g_pts[(size_t)(r + 8) * C_ + cc];
            *(float2*)&g_Ya[(size_t)r * C_ + cc] =
                make_float2(p0.x + ALPHA_F * a4[0], p0.y + ALPHA_F * a4[1]);
            *(float2*)&g_Ya[(size_t)(r + 8) * C_ + cc] =
                make_float2(p1.x + ALPHA_F * a4[2], p1.y + ALPHA_F * a4[3]);
        }
    }
}

// ---------------- 3b) SIMT kernel: Yg = pts @ WgT (exact fp32, f32x2) --------
// 256 CTAs x 128-row tiles, static 32KB smem, 2 CTAs/SM (runs on fma pipe,
// concurrently with gemm_ya via a second captured stream).
#define BM 128
#define BK 16
#define NK (C_ / BK)
__global__ __launch_bounds__(256, 2) void gemm_yg(const float* __restrict__ W) {
    __shared__ float sA[2][BK][BM];
    __shared__ float sW[2][BK][C_];
    const float* A = g_pts;
    int tid = threadIdx.x;
    int tx = tid & 15;
    int ty = tid >> 4;
    int row0 = blockIdx.x * BM;
    int mA0 = tid >> 2, kqA = (tid & 3) * 4;

    u64 acc[8][4];
#pragma unroll
    for (int i = 0; i < 8; ++i)
#pragma unroll
        for (int j = 0; j < 4; ++j) acc[i][j] = 0ull;

    // prologue: tile 0 -> stage 0
#pragma unroll
    for (int r = 0; r < 2; ++r) {
        int m = mA0 + r * 64;
        float4 v = *(const float4*)&A[(size_t)(row0 + m) * C_ + kqA];
        sA[0][kqA + 0][m] = v.x; sA[0][kqA + 1][m] = v.y;
        sA[0][kqA + 2][m] = v.z; sA[0][kqA + 3][m] = v.w;
        float4 w = *(const float4*)&W[(size_t)m * C_ + kqA];
        sW[0][kqA + 0][m] = w.x; sW[0][kqA + 1][m] = w.y;
        sW[0][kqA + 2][m] = w.z; sW[0][kqA + 3][m] = w.w;
    }
    __syncthreads();

    int stage = 0;
    for (int t = 0; t < NK; ++t) {
        float4 nA[2], nW[2];
        if (t < NK - 1) {
            int k0n = (t + 1) * BK;
#pragma unroll
            for (int r = 0; r < 2; ++r) {
                int m = mA0 + r * 64;
                nA[r] = *(const float4*)&A[(size_t)(row0 + m) * C_ + k0n + kqA];
                nW[r] = *(const float4*)&W[(size_t)m * C_ + k0n + kqA];
            }
        }
#pragma unroll
        for (int kk = 0; kk < BK; ++kk) {
            float4 af0 = *(const float4*)&sA[stage][kk][ty * 8];
            float4 af1 = *(const float4*)&sA[stage][kk][ty * 8 + 4];
            u64 ap[8] = {dup2(af0.x), dup2(af0.y), dup2(af0.z), dup2(af0.w),
                         dup2(af1.x), dup2(af1.y), dup2(af1.z), dup2(af1.w)};
            ulonglong2 wq0 = *(const ulonglong2*)&sW[stage][kk][tx * 4];
            ulonglong2 wq1 = *(const ulonglong2*)&sW[stage][kk][64 + tx * 4];
            u64 w[4] = {wq0.x, wq0.y, wq1.x, wq1.y};
#pragma unroll
            for (int i = 0; i < 8; ++i)
#pragma unroll
                for (int j = 0; j < 4; ++j)
                    ffma2(acc[i][j], ap[i], w[j]);
        }
        if (t < NK - 1) {
            int ns = stage ^ 1;
#pragma unroll
            for (int r = 0; r < 2; ++r) {
                int m = mA0 + r * 64;
                sA[ns][kqA + 0][m] = nA[r].x; sA[ns][kqA + 1][m] = nA[r].y;
                sA[ns][kqA + 2][m] = nA[r].z; sA[ns][kqA + 3][m] = nA[r].w;
                sW[ns][kqA + 0][m] = nW[r].x; sW[ns][kqA + 1][m] = nW[r].y;
                sW[ns][kqA + 2][m] = nW[r].z; sW[ns][kqA + 3][m] = nW[r].w;
            }
            __syncthreads();
            stage = ns;
        }
    }
#pragma unroll
    for (int i = 0; i < 8; ++i) {
        size_t base = (size_t)(row0 + ty * 8 + i) * C_;
        float2 g0 = unpack2(acc[i][0]), g1 = unpack2(acc[i][1]);
        float2 g2 = unpack2(acc[i][2]), g3 = unpack2(acc[i][3]);
        *(float4*)&g_Yg[base + tx * 4]      = make_float4(g0.x, g0.y, g1.x, g1.y);
        *(float4*)&g_Yg[base + 64 + tx * 4] = make_float4(g2.x, g2.y, g3.x, g3.y);
    }
}

// ------- 4) gather + residual: pts = Ya + (1-a)*(adj@Yg) ---------------------
__global__ void gather_combine() {
    int node = blockIdx.x * 8 + (threadIdx.x >> 5);
    int lane = threadIdx.x & 31;
    int base = node & ~(N_ - 1);
    const int* nb = g_nbr + (size_t)node * KNN;
    int c = lane * 4;
    float4 acc = make_float4(0.f, 0.f, 0.f, 0.f);
#pragma unroll
    for (int s = 0; s < KNN; ++s) {
        const float4 v = *(const float4*)&g_Yg[(size_t)(base + nb[s]) * C_ + c];
        acc.x += v.x; acc.y += v.y; acc.z += v.z; acc.w += v.w;
    }
    float4 ya = *(const float4*)&g_Ya[(size_t)node * C_ + c];
    float4 o;
    o.x = ya.x + ONEMA_F * (WEDGE_F * acc.x);
    o.y = ya.y + ONEMA_F * (WEDGE_F * acc.y);
    o.z = ya.z + ONEMA_F * (WEDGE_F * acc.z);
    o.w = ya.w + ONEMA_F * (WEDGE_F * acc.w);
    *(float4*)&g_pts[(size_t)node * C_ + c] = o;
}

// ------- 5) unpool projection: Uc = pts@WucT, Ug = pts@WugT (6 outs each) ----
__global__ void unpool_proj(const float* __restrict__ Wuc,
                            const float* __restrict__ Wug) {
    __shared__ float swc[6 * C_], swg[6 * C_];
    for (int i = threadIdx.x; i < 6 * C_; i += 256) { swc[i] = Wuc[i]; swg[i] = Wug[i]; }
    __syncthreads();
    int node = blockIdx.x * 8 + (threadIdx.x >> 5);
    int lane = threadIdx.x & 31;
    float4 p = *(const float4*)&g_pts[(size_t)node * C_ + lane * 4];
#pragma unroll
    for (int o = 0; o < 6; ++o) {
        float4 wc = *(const float4*)&swc[o * C_ + lane * 4];
        float4 wg = *(const float4*)&swg[o * C_ + lane * 4];
        float dc = p.x * wc.x + p.y * wc.y + p.z * wc.z + p.w * wc.w;
        float dg = p.x * wg.x + p.y * wg.y + p.z * wg.z + p.w * wg.w;
#pragma unroll
        for (int off = 16; off; off >>= 1) {
            dc += __shfl_xor_sync(0xffffffffu, dc, off);
            dg += __shfl_xor_sync(0xffffffffu, dg, off);
        }
        if (lane == 0) {
            g_Uc[(size_t)node * 6 + o] = dc;
            g_Ug[(size_t)node * 6 + o] = dg;
        }
    }
}

// ------- 6) finalize new_xyz: a*Uc + (1-a)*(adj@Ug), fold + reshape ----------
__global__ void finalize_xyz(const float* __restrict__ xyz, float* __restrict__ out) {
    int node = blockIdx.x * 256 + threadIdx.x;
    int b = node >> 11, n = node & (N_ - 1);
    int base = node & ~(N_ - 1);
    const int* nb = g_nbr + (size_t)node * KNN;
    float g[6] = {0.f, 0.f, 0.f, 0.f, 0.f, 0.f};
#pragma unroll
    for (int s = 0; s < KNN; ++s) {
        const float* r = g_Ug + (size_t)(base + nb[s]) * 6;
#pragma unroll
        for (int o = 0; o < 6; ++o) g[o] += r[o];
    }
#pragma unroll
    for (int o = 0; o < 6; ++o) {
        float v = ALPHA_F * g_Uc[(size_t)node * 6 + o] + ONEMA_F * (WEDGE_F * g[o]);
        int cdim = o >> 1, t = o & 1;
        out[(size_t)b * 3 * (2 * N_) + cdim * (2 * N_) + t * N_ + n] =
            v + xyz[(size_t)b * 3 * N_ + cdim * N_ + n];
    }
}

// ------- 7) transpose pts (B,N,C) -> output (B,C,N) --------------------------
__global__ void transpose_out(float* __restrict__ out) {
    __shared__ float tile[32][33];
    int b = blockIdx.z;
    int n0 = blockIdx.x * 32, c0 = blockIdx.y * 32;
    const float* src = g_pts + (size_t)b * N_ * C_;
    float* dst = out + (size_t)b * C_ * N_;
    for (int r = threadIdx.y; r < 32; r += 8)
        tile[r][threadIdx.x] = src[(n0 + r) * C_ + c0 + threadIdx.x];
    __syncthreads();
    for (int r = threadIdx.y; r < 32; r += 8)
        dst[(c0 + r) * N_ + n0 + threadIdx.x] = tile[threadIdx.x][r];
}

// -----------------------------------------------------------------------------
static cudaStream_t g_side = nullptr;
static cudaEvent_t  g_evFork = nullptr, g_evJoin = nullptr;

extern "C" void kernel_launch(void* const* d_in, const int* in_sizes, int n_in,
                              void* d_out, int out_size) {
    const float* xyz    = (const float*)d_in[0];   // (16,3,2048)
    const float* points = (const float*)d_in[1];   // (16,128,2048)
    const float* Wc     = (const float*)d_in[2];   // (4,128,128)
    const float* Wg     = (const float*)d_in[3];   // (4,128,128)
    const float* Wuc    = (const float*)d_in[4];   // (6,128)
    const float* Wug    = (const float*)d_in[5];   // (6,128)
    float* out = (float*)d_out;                    // [new_xyz | pts_T] concatenated
    (void)in_sizes; (void)n_in; (void)out_size;

    // one-time resource setup (first call is the non-captured correctness run,
    // so creation never happens during graph capture; handles are reused)
    if (!g_side) {
        cudaStreamCreateWithFlags(&g_side, cudaStreamNonBlocking);
        cudaEventCreateWithFlags(&g_evFork, cudaEventDisableTiming);
        cudaEventCreateWithFlags(&g_evJoin, cudaEventDisableTiming);
        cudaFuncSetAttribute(gemm_ya, cudaFuncAttributeMaxDynamicSharedMemorySize,
                             GEMM_SMEM);
    }

    knn_kernel<<<B_ * 8, 256>>>(xyz, Wc);
    transpose_in<<<dim3(N_ / 32, C_ / 32, B_), dim3(32, 8)>>>(points);
    for (int i = 0; i < NBLK; ++i) {
        // fork: Yg (SIMT/fma pipe) on side stream, Ya (HMMA/tensor pipe) on main
        cudaEventRecord(g_evFork, 0);
        cudaStreamWaitEvent(g_side, g_evFork, 0);
        gemm_yg<<<M_ / BM, 256, 0, g_side>>>(Wg + (size_t)i * C_ * C_);
        gemm_ya<<<M_ / 64, 256, GEMM_SMEM>>>(i);
        // join: gather needs both Ya and Yg
        cudaEventRecord(g_evJoin, g_side);
        cudaStreamWaitEvent((cudaStream_t)0, g_evJoin, 0);
        gather_combine<<<M_ / 8, 256>>>();
    }
    unpool_proj<<<M_ / 8, 256>>>(Wuc, Wug);
    finalize_xyz<<<M_ / 256, 256>>>(xyz, out);
    transpose_out<<<dim3(N_ / 32, C_ / 32, B_), dim3(32, 8)>>>(out + (size_t)B_ * 3 * 2 * N_);
}